// round 12
// baseline (speedup 1.0000x reference)
#include <cuda_runtime.h>

#define NN 32
#define RESOL 256
#define KK 1024
#define NK (NN * KK)
#define EPSF 1e-6f
#define LOG2E 1.4426950408889634f
#define LN2 0.6931471805599453f
#define MAGICF 12582912.0f  // 1.5 * 2^23

// loss tiling (proven): grid = 32 n x 32 chunks; block = 32 j x 1024 i,
// 256 threads = 32 j-lanes x 8 i-octants, 128 i per thread.
#define CHUNKS 32
#define JPB 32
#define IPQ 128  // KK / 8 octants

// Scratch (__device__ globals: allocation-free rule). Coords pre-scaled by log2e.
__device__ float2 g_src[NK];
__device__ float2 g_trg[NK];
__device__ float g_loss, g_viscount;
__device__ int g_mode;
__device__ unsigned int g_done;

__device__ __forceinline__ float sqrt_approx(float x) {
    float r; asm("sqrt.approx.f32 %0, %1;" : "=f"(r) : "f"(x)); return r;
}
// ex2(-x): negation folds into the MUFU source modifier.
__device__ __forceinline__ float ex2_neg(float x) {
    float r;
    asm("{ .reg .f32 t; neg.f32 t, %1; ex2.approx.f32 %0, t; }"
        : "=f"(r) : "f"(x));
    return r;
}
// 2^(-t) for t in [0, ~40] on the FMA/ALU pipes (no MUFU):
// z = t + MAG  -> n = round(t) in low mantissa bits of z
// u = (z - MAG) - t  in [-0.5, 0.5]
// p = 2^u (deg-4 Taylor, rel err ~4e-5); result bits = bits(p) - (bits(z)<<23)
__device__ __forceinline__ float exp2_neg_poly(float t) {
    float z = t + MAGICF;
    float g = z - MAGICF;
    float u = g - t;
    float p = fmaf(0.00961813f, u, 0.05550411f);
    p = fmaf(p, u, 0.24022651f);
    p = fmaf(p, u, 0.69314718f);
    p = fmaf(p, u, 1.0f);
    unsigned zb = __float_as_uint(z);
    unsigned pb = __float_as_uint(p);
    return __uint_as_float(pb - (zb << 23));
}

// ---------------------------------------------------------------------------
// Kernel A: bilinear sampling (grid_sample zeros / align_corners=True),
// outputs scaled by log2e. One thread per (point, field). Block 0 also
// detects kp_vis dtype and zeroes accumulators.
// ---------------------------------------------------------------------------
__device__ __forceinline__ float2 bsample(const float2* __restrict__ flow,
                                          float x, float y) {
    float x0 = floorf(x), y0 = floorf(y);
    float wx = x - x0, wy = y - y0;
    float ax = 0.0f, ay = 0.0f;
#pragma unroll
    for (int dy = 0; dy < 2; dy++) {
#pragma unroll
        for (int dx = 0; dx < 2; dx++) {
            float xi = x0 + (float)dx;
            float yi = y0 + (float)dy;
            bool valid = (xi >= 0.0f) && (xi <= (float)(RESOL - 1)) &&
                         (yi >= 0.0f) && (yi <= (float)(RESOL - 1));
            if (valid) {
                float w = (dx ? wx : 1.0f - wx) * (dy ? wy : 1.0f - wy);
                float2 v = flow[(int)yi * RESOL + (int)xi];
                ax = fmaf(w, v.x, ax);
                ay = fmaf(w, v.y, ay);
            }
        }
    }
    return make_float2(ax, ay);
}

__global__ void __launch_bounds__(256) sample_kernel(
    const float* __restrict__ src_flow, const float* __restrict__ trg_flow,
    const float* __restrict__ src_kp, const float* __restrict__ trg_kp,
    const unsigned char* __restrict__ visraw) {
    if (blockIdx.x == 0) {
        // dtype of serialized bool kp_vis from byte pattern of first 4096 B:
        // u8 -> nonzero at residue 1; f32 1.0f -> residues 2,3; i32 -> residue 0
        __shared__ int s_r1, s_r23;
        if (threadIdx.x == 0) {
            s_r1 = 0; s_r23 = 0;
            g_loss = 0.0f; g_viscount = 0.0f; g_done = 0u;
        }
        __syncthreads();
        int r1 = 0, r23 = 0;
        const int base = threadIdx.x * 16;
#pragma unroll
        for (int k = 0; k < 16; k++) {
            unsigned char b = visraw[base + k];
            if (b) {
                int r = (base + k) & 3;
                if (r == 1) r1 = 1; else if (r >= 2) r23 = 1;
            }
        }
        if (r1) atomicOr(&s_r1, 1);
        if (r23) atomicOr(&s_r23, 1);
        __syncthreads();
        if (threadIdx.x == 0) g_mode = s_r1 ? 0 : (s_r23 ? 2 : 1);
    }

    int idx = blockIdx.x * 256 + threadIdx.x;  // [0, 2*NK)
    bool is_src = idx < NK;
    int p = is_src ? idx : idx - NK;
    int n = p >> 10;
    const float* flow = is_src ? src_flow : trg_flow;
    const float* kp = is_src ? src_kp : trg_kp;
    const float2* fl = (const float2*)(flow + (size_t)n * RESOL * RESOL * 2);
    float2 k2 = ((const float2*)kp)[p];
    float2 c = bsample(fl, k2.x, k2.y);
    float2 cs = make_float2(c.x * LOG2E, c.y * LOG2E);
    if (is_src) g_src[p] = cs; else g_trg[p] = cs;
}

// ---------------------------------------------------------------------------
// Kernel B: loss + fused finalize. Proven structure; split-pipe exp:
//   even pairs: MUFU.SQRT + MUFU.EX2(-t)
//   odd pairs:  MUFU.SQRT + fma-pipe poly 2^(-t)   -> 1.5 MUFU/pair
// loss_j = ln2 * tjj + log( sum_i exp2 );  d1==d2 forward -> x2.
// ---------------------------------------------------------------------------
__global__ void __launch_bounds__(256) loss_kernel(
    const unsigned char* __restrict__ visraw,
    const float* __restrict__ kp_wt, float* __restrict__ out) {
    __shared__ float2 s_src[KK];
    __shared__ float s_sum[JPB];

    const int n = blockIdx.x >> 5;        // / CHUNKS
    const int chunk = blockIdx.x & 31;    // % CHUNKS
    const int tid = threadIdx.x;

    {   // stage src[n] (8 KB) via float4
        const float4* g4 = (const float4*)(g_src + n * KK);
        float4* s4 = (float4*)s_src;
#pragma unroll
        for (int k = 0; k < 2; k++) s4[tid + 256 * k] = g4[tid + 256 * k];
    }
    if (tid < JPB) s_sum[tid] = 0.0f;
    __syncthreads();

    const int jl = tid & 31;
    const int q = tid >> 5;               // warp id = i-octant
    const int j = chunk * JPB + jl;

    const float2 t = g_trg[n * KK + j];
    const float txe = t.x - EPSF * LOG2E;  // dx = sx - txe (eps folded)
    const float tye = t.y - EPSF * LOG2E;

    float sum0 = 0.0f, sum1 = 0.0f;
    const int i0 = q * IPQ;
#pragma unroll
    for (int ii = 0; ii < IPQ; ii += 2) {
        {   // even pair: full MUFU path
            float2 s = s_src[i0 + ii];     // warp-uniform LDS.64, imm offset
            float dx = s.x - txe;
            float dy = s.y - tye;
            float ss = fmaf(dx, dx, dy * dy);
            float tt = sqrt_approx(ss);    // MUFU.SQRT -> d*log2e
            sum0 += ex2_neg(tt);           // MUFU.EX2 (-src)
        }
        {   // odd pair: MUFU.SQRT + fma-pipe poly exp2
            float2 s = s_src[i0 + ii + 1];
            float dx = s.x - txe;
            float dy = s.y - tye;
            float ss = fmaf(dx, dx, dy * dy);
            float tt = sqrt_approx(ss);    // MUFU.SQRT
            sum1 += exp2_neg_poly(tt);     // FADD/FFMA/ALU only
        }
    }
    atomicAdd(&s_sum[jl], sum0 + sum1);
    __syncthreads();

    if (tid < JPB) {  // warp 0: jl == tid, txe/tye already this thread's j
        float2 s = s_src[j];
        float dx = s.x - txe;
        float dy = s.y - tye;
        float tjj = sqrt_approx(fmaf(dx, dx, dy * dy));  // d(j,j)*log2e

        const int jg = n * KK + j;
        const int m = g_mode;
        bool v;
        if (m == 0)      v = visraw[jg] != 0;
        else if (m == 1) v = ((const int*)visraw)[jg] != 0;
        else             v = ((const float*)visraw)[jg] != 0.0f;
        float visf = v ? 1.0f : 0.0f;

        float val = (LN2 * tjj + __logf(s_sum[tid])) * visf * kp_wt[jg];
#pragma unroll
        for (int off = 16; off; off >>= 1) {
            val  += __shfl_down_sync(0xFFFFFFFFu, val, off);
            visf += __shfl_down_sync(0xFFFFFFFFu, visf, off);
        }
        if (tid == 0) {
            atomicAdd(&g_loss, val);
            atomicAdd(&g_viscount, visf);
            __threadfence();
            unsigned int ticket = atomicAdd(&g_done, 1u);
            if (ticket == gridDim.x - 1) {
                float L = *((volatile float*)&g_loss);
                float V = *((volatile float*)&g_viscount);
                out[0] = 2.0f * L / V;
            }
        }
    }
}

extern "C" void kernel_launch(void* const* d_in, const int* in_sizes, int n_in,
                              void* d_out, int out_size) {
    (void)in_sizes; (void)n_in; (void)out_size;
    const float* src_flow = (const float*)d_in[0];
    const float* trg_flow = (const float*)d_in[1];
    const float* src_kp   = (const float*)d_in[2];
    const float* trg_kp   = (const float*)d_in[3];
    const unsigned char* kp_vis = (const unsigned char*)d_in[4];
    const float* kp_wt    = (const float*)d_in[5];
    float* out = (float*)d_out;

    cudaFuncSetAttribute(loss_kernel,
                         cudaFuncAttributePreferredSharedMemoryCarveout, 100);

    sample_kernel<<<2 * NK / 256, 256>>>(src_flow, trg_flow, src_kp, trg_kp, kp_vis);
    loss_kernel<<<NN * CHUNKS, 256>>>(kp_vis, kp_wt, out);
}